// round 6
// baseline (speedup 1.0000x reference)
#include <cuda_runtime.h>
#include <cuda_bf16.h>
#include <math.h>

// Problem constants
#define T_TOKENS   16384
#define HID        4096
#define NEXP       64
#define TOPK       8
#define RSCALE     2.5f

// Tiling
#define TM    128           // tokens per block
#define KB    32            // k-chunk per smem stage (TwoSum super-chunk)
#define NTH   256           // threads per block (8 warps, 16 tokens each)
#define NKT   (HID / KB)    // 128 k-tiles

// dynamic smem layout (floats):
//   stage st (st=0,1), each 8192 floats (32KB):
//     xs : [st*8192 + kk*128 + tok]            (KB x TM, transposed x)
//     wsd: [st*8192 + 4096 + kk*128 + col]     (KB x 2*NEXP, duplicated W)
//   epilogue (after all stage reads): sc[tok*65 + e]
#define STF   8192
#define XSOFF 0
#define WSOFF 4096

typedef unsigned long long ull;

__device__ __forceinline__ ull ffma2(ull a, ull b, ull c) {
    ull d;
    asm("fma.rn.f32x2 %0, %1, %2, %3;" : "=l"(d) : "l"(a), "l"(b), "l"(c));
    return d;
}
__device__ __forceinline__ ull add2(ull a, ull b) {
    ull d;
    asm("add.rn.f32x2 %0, %1, %2;" : "=l"(d) : "l"(a), "l"(b));
    return d;
}
__device__ __forceinline__ ull pack2(float x) {
    ull d;
    asm("mov.b64 %0, {%1, %1};" : "=l"(d) : "f"(x));
    return d;
}
__device__ __forceinline__ void unpack2(ull v, float& lo, float& hi) {
    asm("mov.b64 {%0, %1}, %2;" : "=f"(lo), "=f"(hi) : "l"(v));
}
// packed lanewise a - b = fma(b, -1, a)  (exact)
__device__ __forceinline__ ull sub2(ull a, ull b, ull NEG1) {
    return ffma2(b, NEG1, a);
}

__global__ __launch_bounds__(NTH, 1)
void moe_gate_kernel(const float* __restrict__ x,
                     const float* __restrict__ W,
                     const float* __restrict__ bias,
                     float* __restrict__ out)
{
    extern __shared__ float dsm[];
    __shared__ float bias_s[NEXP];

    const int tid  = threadIdx.x;
    const int lane = tid & 31;
    const int wid  = tid >> 5;          // 0..7
    const int tok0 = wid * 16;          // warp's 16 tokens
    const int t0   = blockIdx.x * TM;
    const float* xg = x + (size_t)t0 * HID;

    if (tid < NEXP) bias_s[tid] = bias[tid];

    // prefetch mapping:
    //   x tile: 1024 float4, 4 per thread (flat = tid + p*256): tok = f>>3, kq = f&7
    //   W tile: 512 float4, 2 per thread (flat = tid + p*256): row = f>>4, c4 = f&15
    // ---- prologue: fill stage 0
    {
        float* XS = dsm + XSOFF;
        float* WD = dsm + WSOFF;
        #pragma unroll
        for (int p = 0; p < 4; ++p) {
            int f   = tid + p * NTH;
            int tok = f >> 3;
            int kq  = (f & 7) * 4;
            float4 v = *(const float4*)(xg + (size_t)tok * HID + kq);
            XS[(kq + 0) * 128 + tok] = v.x;
            XS[(kq + 1) * 128 + tok] = v.y;
            XS[(kq + 2) * 128 + tok] = v.z;
            XS[(kq + 3) * 128 + tok] = v.w;
        }
        #pragma unroll
        for (int p = 0; p < 2; ++p) {
            int f   = tid + p * NTH;
            int row = f >> 4;
            int c4  = (f & 15) * 4;
            float4 v = *(const float4*)(W + (size_t)row * NEXP + c4);
            float4 d0 = make_float4(v.x, v.x, v.y, v.y);
            float4 d1 = make_float4(v.z, v.z, v.w, v.w);
            *(float4*)&WD[row * 128 + c4 * 2]     = d0;
            *(float4*)&WD[row * 128 + c4 * 2 + 4] = d1;
        }
    }

    const ull NEG1 = pack2(-1.0f);

    // compensated accumulators: 8 token-pairs x 2 experts (e0=lane, e1=lane+32)
    ull s[8][2], c[8][2];
    #pragma unroll
    for (int p = 0; p < 8; ++p)
        #pragma unroll
        for (int j = 0; j < 2; ++j) { s[p][j] = 0ull; c[p][j] = 0ull; }

    for (int kt = 0; kt < NKT; ++kt) {
        // ---- prefetch next tile into registers
        float4 pvx[4], pvw[2];
        const bool pf = (kt + 1 < NKT);
        if (pf) {
            const float* xb = xg + (kt + 1) * KB;
            #pragma unroll
            for (int p = 0; p < 4; ++p) {
                int f   = tid + p * NTH;
                int tok = f >> 3;
                int kq  = (f & 7) * 4;
                pvx[p] = *(const float4*)(xb + (size_t)tok * HID + kq);
            }
            #pragma unroll
            for (int p = 0; p < 2; ++p) {
                int f   = tid + p * NTH;
                int row = (kt + 1) * KB + (f >> 4);
                int c4  = (f & 15) * 4;
                pvw[p] = *(const float4*)(W + (size_t)row * NEXP + c4);
            }
        }
        __syncthreads();   // stage (kt&1) published
        const float* XS = dsm + (kt & 1) * STF + XSOFF;
        const float* WD = dsm + (kt & 1) * STF + WSOFF;

        // ---- compute: 4 subs of 8-term FFMA2 chains, add2 tree, TwoSum per 32 terms
        ull u[8][2];
        #pragma unroll
        for (int sub = 0; sub < 4; ++sub) {
            ull t[8][2];
            #pragma unroll
            for (int p = 0; p < 8; ++p)
                #pragma unroll
                for (int j = 0; j < 2; ++j) t[p][j] = 0ull;

            #pragma unroll
            for (int q = 0; q < 8; ++q) {
                const int kk = sub * 8 + q;
                // b: duplicated W pairs, direct packed operand (no mov)
                ull b0 = *(const ull*)&WD[kk * 128 + 2 * lane];        // expert lane
                ull b1 = *(const ull*)&WD[kk * 128 + 2 * lane + 64];   // expert lane+32
                // a: warp-uniform broadcast, packed token pairs
                ulonglong2 xa = *(const ulonglong2*)&XS[kk * 128 + tok0];
                ulonglong2 xb2 = *(const ulonglong2*)&XS[kk * 128 + tok0 + 4];
                ulonglong2 xc = *(const ulonglong2*)&XS[kk * 128 + tok0 + 8];
                ulonglong2 xd = *(const ulonglong2*)&XS[kk * 128 + tok0 + 12];
                ull a[8] = {xa.x, xa.y, xb2.x, xb2.y, xc.x, xc.y, xd.x, xd.y};
                #pragma unroll
                for (int p = 0; p < 8; ++p) {
                    t[p][0] = ffma2(a[p], b0, t[p][0]);
                    t[p][1] = ffma2(a[p], b1, t[p][1]);
                }
            }
            #pragma unroll
            for (int p = 0; p < 8; ++p)
                #pragma unroll
                for (int j = 0; j < 2; ++j)
                    u[p][j] = (sub == 0) ? t[p][j] : add2(u[p][j], t[p][j]);
        }

        // TwoSum: (s, c) += u   (branchless Knuth, lanewise packed)
        #pragma unroll
        for (int p = 0; p < 8; ++p)
            #pragma unroll
            for (int j = 0; j < 2; ++j) {
                ull sp = add2(s[p][j], u[p][j]);
                ull z  = sub2(sp, s[p][j], NEG1);
                ull e1 = sub2(u[p][j], z, NEG1);
                ull t2 = sub2(sp, z, NEG1);
                ull e2 = sub2(s[p][j], t2, NEG1);
                c[p][j] = add2(c[p][j], add2(e1, e2));
                s[p][j] = sp;
            }

        // ---- store prefetched tile into the other stage
        if (pf) {
            float* XN = dsm + ((kt + 1) & 1) * STF + XSOFF;
            float* WN = dsm + ((kt + 1) & 1) * STF + WSOFF;
            #pragma unroll
            for (int p = 0; p < 4; ++p) {
                int f   = tid + p * NTH;
                int tok = f >> 3;
                int kq  = (f & 7) * 4;
                XN[(kq + 0) * 128 + tok] = pvx[p].x;
                XN[(kq + 1) * 128 + tok] = pvx[p].y;
                XN[(kq + 2) * 128 + tok] = pvx[p].z;
                XN[(kq + 3) * 128 + tok] = pvx[p].w;
            }
            #pragma unroll
            for (int p = 0; p < 2; ++p) {
                int f   = tid + p * NTH;
                int row = f >> 4;
                int c4  = (f & 15) * 4;
                float4 v = pvw[p];
                float4 d0 = make_float4(v.x, v.x, v.y, v.y);
                float4 d1 = make_float4(v.z, v.z, v.w, v.w);
                *(float4*)&WN[row * 128 + c4 * 2]     = d0;
                *(float4*)&WN[row * 128 + c4 * 2 + 4] = d1;
            }
        }
    }

    __syncthreads();  // stage reads done; dsm reused as score matrix sc[tok*65+e]

    // ---- epilogue: logits = s + c, sigmoid, write scores
    #pragma unroll
    for (int p = 0; p < 8; ++p) {
        #pragma unroll
        for (int j = 0; j < 2; ++j) {
            float lo, hi;
            unpack2(add2(s[p][j], c[p][j]), lo, hi);
            const int e = lane + j * 32;
            dsm[(tok0 + 2 * p    ) * 65 + e] = 1.0f / (1.0f + expf(-lo));
            dsm[(tok0 + 2 * p + 1) * 65 + e] = 1.0f / (1.0f + expf(-hi));
        }
    }
    __syncthreads();

    // ---- top-8 per token (stable: ties keep lowest expert index first)
    if (tid < TM) {
        const int tok = tid;
        const float* sc = dsm + tok * 65;
        float bv[TOPK];
        int   bi[TOPK];
        #pragma unroll
        for (int k = 0; k < TOPK; ++k) { bv[k] = -INFINITY; bi[k] = 0; }

        for (int e = 0; e < NEXP; ++e) {
            float sv = sc[e] + bias_s[e];
            if (sv > bv[TOPK - 1]) {
                bv[TOPK - 1] = sv; bi[TOPK - 1] = e;
                #pragma unroll
                for (int j = TOPK - 1; j > 0; --j) {
                    if (bv[j] > bv[j - 1]) {
                        float tv = bv[j]; bv[j] = bv[j - 1]; bv[j - 1] = tv;
                        int   ti = bi[j]; bi[j] = bi[j - 1]; bi[j - 1] = ti;
                    }
                }
            }
        }

        float wsel[TOPK];
        float sum = 1e-20f;
        #pragma unroll
        for (int k = 0; k < TOPK; ++k) {
            wsel[k] = sc[bi[k]];
            sum += wsel[k];
        }
        float inv = RSCALE / sum;

        const size_t gt = (size_t)(t0 + tok);
        float* out_idx = out + gt * TOPK;
        float* out_w   = out + (size_t)T_TOKENS * TOPK + gt * TOPK;
        #pragma unroll
        for (int k = 0; k < TOPK; ++k) {
            out_idx[k] = (float)bi[k];
            out_w[k]   = wsel[k] * inv;
        }
    }
}

extern "C" void kernel_launch(void* const* d_in, const int* in_sizes, int n_in,
                              void* d_out, int out_size)
{
    const float* x    = (const float*)d_in[0];
    const float* W    = (const float*)d_in[1];
    const float* bias = (const float*)d_in[2];
    float* out = (float*)d_out;

    const int smem_bytes = 2 * STF * (int)sizeof(float);   // 65536
    cudaFuncSetAttribute(moe_gate_kernel,
                         cudaFuncAttributeMaxDynamicSharedMemorySize, smem_bytes);

    dim3 grid(T_TOKENS / TM);
    dim3 block(NTH);
    moe_gate_kernel<<<grid, block, smem_bytes>>>(x, W, bias, out);
}

// round 7
// speedup vs baseline: 1.0223x; 1.0223x over previous
#include <cuda_runtime.h>
#include <cuda_bf16.h>
#include <math.h>

// Problem constants
#define T_TOKENS   16384
#define HID        4096
#define NEXP       64
#define TOPK       8
#define RSCALE     2.5f

// Tiling (R5 shape: 512 threads, warp = 8 tokens x 64 experts) + duplicated-W smem
#define TM    128           // tokens per block
#define KB    32            // k-chunk per smem stage (TwoSum super-chunk)
#define NTH   512           // threads per block (16 warps)
#define NKT   (HID / KB)    // 128 k-tiles

// dynamic smem layout (floats), per stage (32KB):
//   xs : [kk*128 + tok]          KB x TM   transposed x
//   wsd: [4096 + kk*128 + col]   KB x 128  duplicated W: col 2e,2e+1 = W[k][e]
#define STF   8192
#define XSOFF 0
#define WSOFF 4096

typedef unsigned long long ull;

__device__ __forceinline__ ull ffma2(ull a, ull b, ull c) {
    ull d;
    asm("fma.rn.f32x2 %0, %1, %2, %3;" : "=l"(d) : "l"(a), "l"(b), "l"(c));
    return d;
}
__device__ __forceinline__ ull add2(ull a, ull b) {
    ull d;
    asm("add.rn.f32x2 %0, %1, %2;" : "=l"(d) : "l"(a), "l"(b));
    return d;
}
__device__ __forceinline__ ull pack2(float x) {
    ull d;
    asm("mov.b64 %0, {%1, %1};" : "=l"(d) : "f"(x));
    return d;
}
__device__ __forceinline__ void unpack2(ull v, float& lo, float& hi) {
    asm("mov.b64 {%0, %1}, %2;" : "=f"(lo), "=f"(hi) : "l"(v));
}
// packed lanewise a - b = fma(b, -1, a)  (exact)
__device__ __forceinline__ ull sub2(ull a, ull b, ull NEG1) {
    return ffma2(b, NEG1, a);
}

__global__ __launch_bounds__(NTH, 1)
void moe_gate_kernel(const float* __restrict__ x,
                     const float* __restrict__ W,
                     const float* __restrict__ bias,
                     float* __restrict__ out)
{
    extern __shared__ float dsm[];
    __shared__ float bias_s[NEXP];

    const int tid  = threadIdx.x;
    const int lane = tid & 31;
    const int wid  = tid >> 5;          // 0..15
    const int tok0 = wid * 8;           // warp's 8 tokens
    const int t0   = blockIdx.x * TM;
    const float* xg = x + (size_t)t0 * HID;

    if (tid < NEXP) bias_s[tid] = bias[tid];

    // prefetch mapping:
    //   x tile: 1024 float4, 2/thread:  f = tid*2+p   -> tok = f>>3, kq = (f&7)*4
    //   W tile: 512 float4, 1/thread:   row = tid>>4, c4 = (tid&15)*4
    const int xf0   = tid * 2;
    const int xtok0 = xf0 >> 3;
    const int xk0   = (xf0 & 7) * 4;
    const int xf1   = xf0 + 1;
    const int xtok1 = xf1 >> 3;
    const int xk1   = (xf1 & 7) * 4;
    const int wrow  = tid >> 4;
    const int wcol  = (tid & 15) * 4;

    // ---- prologue: fill stage 0
    {
        float4 v0 = *(const float4*)(xg + (size_t)xtok0 * HID + xk0);
        float4 v1 = *(const float4*)(xg + (size_t)xtok1 * HID + xk1);
        float4 wv = *(const float4*)(W + (size_t)wrow * NEXP + wcol);
        float* XS = dsm + XSOFF;
        float* WD = dsm + WSOFF;
        XS[(xk0 + 0) * 128 + xtok0] = v0.x;  XS[(xk0 + 1) * 128 + xtok0] = v0.y;
        XS[(xk0 + 2) * 128 + xtok0] = v0.z;  XS[(xk0 + 3) * 128 + xtok0] = v0.w;
        XS[(xk1 + 0) * 128 + xtok1] = v1.x;  XS[(xk1 + 1) * 128 + xtok1] = v1.y;
        XS[(xk1 + 2) * 128 + xtok1] = v1.z;  XS[(xk1 + 3) * 128 + xtok1] = v1.w;
        float4 d0 = make_float4(wv.x, wv.x, wv.y, wv.y);
        float4 d1 = make_float4(wv.z, wv.z, wv.w, wv.w);
        *(float4*)&WD[wrow * 128 + wcol * 2]     = d0;
        *(float4*)&WD[wrow * 128 + wcol * 2 + 4] = d1;
    }

    const ull NEG1 = pack2(-1.0f);

    // compensated accumulators: 4 token-pairs x 2 experts (e0=lane, e1=lane+32)
    ull s[4][2], c[4][2];
    #pragma unroll
    for (int p = 0; p < 4; ++p)
        #pragma unroll
        for (int j = 0; j < 2; ++j) { s[p][j] = 0ull; c[p][j] = 0ull; }

    for (int kt = 0; kt < NKT; ++kt) {
        // ---- prefetch next tile into registers
        float4 pv0, pv1, pw;
        const bool pf = (kt + 1 < NKT);
        if (pf) {
            const float* xb = xg + (kt + 1) * KB;
            pv0 = *(const float4*)(xb + (size_t)xtok0 * HID + xk0);
            pv1 = *(const float4*)(xb + (size_t)xtok1 * HID + xk1);
            pw  = *(const float4*)(W + (size_t)((kt + 1) * KB + wrow) * NEXP + wcol);
        }
        __syncthreads();   // stage (kt&1) published
        const float* XS = dsm + (kt & 1) * STF + XSOFF;
        const float* WD = dsm + (kt & 1) * STF + WSOFF;

        // ---- compute: 4 subs of 8-term FFMA2 chains, add2 tree, TwoSum per 32 terms
        ull u[4][2];
        #pragma unroll
        for (int sub = 0; sub < 4; ++sub) {
            ull t[4][2];
            #pragma unroll
            for (int p = 0; p < 4; ++p)
                #pragma unroll
                for (int j = 0; j < 2; ++j) t[p][j] = 0ull;

            #pragma unroll
            for (int q = 0; q < 8; ++q) {
                const int kk = sub * 8 + q;
                // b: duplicated W pairs -> direct packed operand (no pack2 mov)
                ull b0 = *(const ull*)&WD[kk * 128 + 2 * lane];        // expert lane
                ull b1 = *(const ull*)&WD[kk * 128 + 2 * lane + 64];   // expert lane+32
                // a: warp-uniform broadcast, packed token pairs
                ulonglong2 xa  = *(const ulonglong2*)&XS[kk * 128 + tok0];
                ulonglong2 xb2 = *(const ulonglong2*)&XS[kk * 128 + tok0 + 4];
                ull a[4] = {xa.x, xa.y, xb2.x, xb2.y};
                #pragma unroll
                for (int p = 0; p < 4; ++p) {
                    t[p][0] = ffma2(a[p], b0, t[p][0]);
                    t[p][1] = ffma2(a[p], b1, t[p][1]);
                }
            }
            #pragma unroll
            for (int p = 0; p < 4; ++p)
                #pragma unroll
                for (int j = 0; j < 2; ++j)
                    u[p][j] = (sub == 0) ? t[p][j] : add2(u[p][j], t[p][j]);
        }

        // TwoSum: (s, c) += u   (branchless Knuth, lanewise packed)
        #pragma unroll
        for (int p = 0; p < 4; ++p)
            #pragma unroll
            for (int j = 0; j < 2; ++j) {
                ull sp = add2(s[p][j], u[p][j]);
                ull z  = sub2(sp, s[p][j], NEG1);
                ull e1 = sub2(u[p][j], z, NEG1);
                ull t2 = sub2(sp, z, NEG1);
                ull e2 = sub2(s[p][j], t2, NEG1);
                c[p][j] = add2(c[p][j], add2(e1, e2));
                s[p][j] = sp;
            }

        // ---- store prefetched tile into the other stage
        if (pf) {
            float* XN = dsm + ((kt + 1) & 1) * STF + XSOFF;
            float* WN = dsm + ((kt + 1) & 1) * STF + WSOFF;
            XN[(xk0 + 0) * 128 + xtok0] = pv0.x;  XN[(xk0 + 1) * 128 + xtok0] = pv0.y;
            XN[(xk0 + 2) * 128 + xtok0] = pv0.z;  XN[(xk0 + 3) * 128 + xtok0] = pv0.w;
            XN[(xk1 + 0) * 128 + xtok1] = pv1.x;  XN[(xk1 + 1) * 128 + xtok1] = pv1.y;
            XN[(xk1 + 2) * 128 + xtok1] = pv1.z;  XN[(xk1 + 3) * 128 + xtok1] = pv1.w;
            float4 d0 = make_float4(pw.x, pw.x, pw.y, pw.y);
            float4 d1 = make_float4(pw.z, pw.z, pw.w, pw.w);
            *(float4*)&WN[wrow * 128 + wcol * 2]     = d0;
            *(float4*)&WN[wrow * 128 + wcol * 2 + 4] = d1;
        }
    }

    __syncthreads();  // stage reads done; dsm reused as score matrix sc[tok*65+e]

    // ---- epilogue: logits = s + c, sigmoid, write scores
    #pragma unroll
    for (int p = 0; p < 4; ++p) {
        #pragma unroll
        for (int j = 0; j < 2; ++j) {
            float lo, hi;
            unpack2(add2(s[p][j], c[p][j]), lo, hi);
            const int e = lane + j * 32;
            dsm[(tok0 + 2 * p    ) * 65 + e] = 1.0f / (1.0f + expf(-lo));
            dsm[(tok0 + 2 * p + 1) * 65 + e] = 1.0f / (1.0f + expf(-hi));
        }
    }
    __syncthreads();

    // ---- top-8 per token (stable: ties keep lowest expert index first)
    if (tid < TM) {
        const int tok = tid;
        const float* sc = dsm + tok * 65;
        float bv[TOPK];
        int   bi[TOPK];
        #pragma unroll
        for (int k = 0; k < TOPK; ++k) { bv[k] = -INFINITY; bi[k] = 0; }

        for (int e = 0; e < NEXP; ++e) {
            float sv = sc[e] + bias_s[e];
            if (sv > bv[TOPK - 1]) {
                bv[TOPK - 1] = sv; bi[TOPK - 1] = e;
                #pragma unroll
                for (int j = TOPK - 1; j > 0; --j) {
                    if (bv[j] > bv[j - 1]) {
                        float tv = bv[j]; bv[j] = bv[j - 1]; bv[j - 1] = tv;
                        int   ti = bi[j]; bi[j] = bi[j - 1]; bi[j - 1] = ti;
                    }
                }
            }
        }

        float wsel[TOPK];
        float sum = 1e-20f;
        #pragma unroll
        for (int k = 0; k < TOPK; ++k) {
            wsel[k] = sc[bi[k]];
            sum += wsel[k];
        }
        float inv = RSCALE / sum;

        const size_t gt = (size_t)(t0 + tok);
        float* out_idx = out + gt * TOPK;
        float* out_w   = out + (size_t)T_TOKENS * TOPK + gt * TOPK;
        #pragma unroll
        for (int k = 0; k < TOPK; ++k) {
            out_idx[k] = (float)bi[k];
            out_w[k]   = wsel[k] * inv;
        }
    }
}

extern "C" void kernel_launch(void* const* d_in, const int* in_sizes, int n_in,
                              void* d_out, int out_size)
{
    const float* x    = (const float*)d_in[0];
    const float* W    = (const float*)d_in[1];
    const float* bias = (const float*)d_in[2];
    float* out = (float*)d_out;

    const int smem_bytes = 2 * STF * (int)sizeof(float);   // 65536
    cudaFuncSetAttribute(moe_gate_kernel,
                         cudaFuncAttributeMaxDynamicSharedMemorySize, smem_bytes);

    dim3 grid(T_TOKENS / TM);
    dim3 block(NTH);
    moe_gate_kernel<<<grid, block, smem_bytes>>>(x, W, bias, out);
}

// round 9
// speedup vs baseline: 2.1438x; 2.0971x over previous
#include <cuda_runtime.h>
#include <cuda_bf16.h>
#include <math.h>
#include <stdint.h>

// Problem constants
#define T_TOKENS 16384
#define HID      4096
#define NEXP     64
#define TOPK     8
#define RSCALE   2.5f

// Tiling
#define TM    128            // tokens per CTA
#define KBLK  64             // k per stage
#define NKB   (HID / KBLK)   // 64 stages
#define NTH   512            // 16 warps: wm = wid&7 (m16 tile), wn = wid>>3 (n32 half)

// near-tie refinement threshold (biased-score space); tc score err sigma ~1e-6
#define THETA 1.2e-5f

// stage layout (bytes): all rows are 128B, 16B-granule XOR swizzle
#define XHOFF 0        // x hi: 128 tok x 64 bf16 (16KB)
#define XLOFF 16384    // x lo (16KB)
#define WHOFF 32768    // W hi: 64 k x 64 exp bf16 (8KB)
#define WLOFF 40960    // W lo (8KB)
#define STAGE_BYTES 49152
#define SMEM_TOTAL  (2 * STAGE_BYTES)

__device__ int g_refine_cnt;
__device__ int g_refine_list[T_TOKENS];

// ---------------- helpers ----------------
__device__ __forceinline__ uint32_t smem_u32(const void* p) {
    uint32_t a;
    asm("{ .reg .u64 t; cvta.to.shared.u64 t, %1; cvt.u32.u64 %0, t; }" : "=r"(a) : "l"(p));
    return a;
}
__device__ __forceinline__ void ldsm4(uint32_t* r, uint32_t addr) {
    asm volatile("ldmatrix.sync.aligned.m8n8.x4.shared.b16 {%0,%1,%2,%3}, [%4];"
                 : "=r"(r[0]), "=r"(r[1]), "=r"(r[2]), "=r"(r[3]) : "r"(addr));
}
__device__ __forceinline__ void ldsm4t(uint32_t* r, uint32_t addr) {
    asm volatile("ldmatrix.sync.aligned.m8n8.x4.trans.shared.b16 {%0,%1,%2,%3}, [%4];"
                 : "=r"(r[0]), "=r"(r[1]), "=r"(r[2]), "=r"(r[3]) : "r"(addr));
}
__device__ __forceinline__ void mma16816(float* c, const uint32_t* a, uint32_t b0, uint32_t b1) {
    asm volatile(
        "mma.sync.aligned.m16n8k16.row.col.f32.bf16.bf16.f32 "
        "{%0,%1,%2,%3}, {%4,%5,%6,%7}, {%8,%9}, {%0,%1,%2,%3};"
        : "+f"(c[0]), "+f"(c[1]), "+f"(c[2]), "+f"(c[3])
        : "r"(a[0]), "r"(a[1]), "r"(a[2]), "r"(a[3]), "r"(b0), "r"(b1));
}
// exact 2-term bf16 split of two floats -> packed hi, lo (low half = first elem)
__device__ __forceinline__ void split2(float f0, float f1, uint32_t& h, uint32_t& l) {
    __nv_bfloat16 h0 = __float2bfloat16_rn(f0);
    __nv_bfloat16 h1 = __float2bfloat16_rn(f1);
    float r0 = __fsub_rn(f0, __bfloat162float(h0));
    float r1 = __fsub_rn(f1, __bfloat162float(h1));
    __nv_bfloat162 hh; hh.x = h0; hh.y = h1;
    __nv_bfloat162 ll; ll.x = __float2bfloat16_rn(r0); ll.y = __float2bfloat16_rn(r1);
    h = *(uint32_t*)&hh;
    l = *(uint32_t*)&ll;
}
__device__ __forceinline__ void split8(float4 a, float4 b, uint4& hi, uint4& lo) {
    split2(a.x, a.y, hi.x, lo.x);
    split2(a.z, a.w, hi.y, lo.y);
    split2(b.x, b.y, hi.z, lo.z);
    split2(b.z, b.w, hi.w, lo.w);
}

__global__ void reset_cnt_kernel() { g_refine_cnt = 0; }

// ---------------- store one k-block into a stage ----------------
__device__ __forceinline__ void store_stage(char* stage, const float4* xv,
                                            const float4* wv, int tid)
{
    // x: 2 units/thread; unit u: tok = u>>3, c8 = u&7 (8 consecutive k)
    #pragma unroll
    for (int p = 0; p < 2; ++p) {
        int u   = tid + p * NTH;
        int tok = u >> 3;
        int c8  = u & 7;
        uint4 hi, lo;
        split8(xv[p * 2], xv[p * 2 + 1], hi, lo);
        uint32_t off = (uint32_t)tok * 128 + (((uint32_t)c8 * 16) ^ (((uint32_t)tok & 7) << 4));
        *(uint4*)(stage + XHOFF + off) = hi;
        *(uint4*)(stage + XLOFF + off) = lo;
    }
    // W: 1 unit/thread: row = tid>>3 (k-row), u8 = tid&7 (8 experts)
    {
        int row = tid >> 3;
        int u8  = tid & 7;
        uint4 hi, lo;
        split8(wv[0], wv[1], hi, lo);
        uint32_t off = (uint32_t)row * 128 + (((uint32_t)u8 * 16) ^ (((uint32_t)row & 7) << 4));
        *(uint4*)(stage + WHOFF + off) = hi;
        *(uint4*)(stage + WLOFF + off) = lo;
    }
}
__device__ __forceinline__ void load_gmem(float4* xv, float4* wv, const float* xg,
                                          const float* W, int kb, int tid)
{
    const int k0 = kb * KBLK;
    #pragma unroll
    for (int p = 0; p < 2; ++p) {
        int u   = tid + p * NTH;
        int tok = u >> 3;
        int c8  = (u & 7) * 8;
        const float* src = xg + (size_t)tok * HID + k0 + c8;
        xv[p * 2]     = *(const float4*)(src);
        xv[p * 2 + 1] = *(const float4*)(src + 4);
    }
    {
        int row = tid >> 3;
        int e8  = (tid & 7) * 8;
        const float* src = W + (size_t)(k0 + row) * NEXP + e8;
        wv[0] = *(const float4*)(src);
        wv[1] = *(const float4*)(src + 4);
    }
}

// ---------------- kernel 1: MMA gate ----------------
__global__ __launch_bounds__(NTH, 1)
void moe_gate_mma_kernel(const float* __restrict__ x,
                         const float* __restrict__ W,
                         const float* __restrict__ bias,
                         float* __restrict__ out)
{
    extern __shared__ char dsm[];
    __shared__ float bias_s[NEXP];

    const int tid  = threadIdx.x;
    const int lane = tid & 31;
    const int wid  = tid >> 5;
    const int wm   = wid & 7;    // m16 tile: tokens [wm*16, wm*16+16)
    const int wn   = wid >> 3;   // n32 half: experts [wn*32, wn*32+32)
    const int t0   = blockIdx.x * TM;
    const float* xg = x + (size_t)t0 * HID;

    if (tid < NEXP) bias_s[tid] = bias[tid];

    // accumulators: 4 n8-tiles x 4 fp32 frag regs
    float acc[4][4];
    #pragma unroll
    for (int n = 0; n < 4; ++n)
        #pragma unroll
        for (int i = 0; i < 4; ++i) acc[n][i] = 0.0f;

    // prologue: stage 0
    {
        float4 xv[4], wv[2];
        load_gmem(xv, wv, xg, W, 0, tid);
        store_stage(dsm, xv, wv, tid);
    }

    const uint32_t sb0     = smem_u32(dsm);
    const int      tokrow  = wm * 16 + (lane & 15);
    const uint32_t half16  = ((uint32_t)lane >> 4) * 16;
    const uint32_t swA     = ((uint32_t)tokrow & 7) << 4;

    for (int kb = 0; kb < NKB; ++kb) {
        float4 xv[4], wv[2];
        const bool pf = (kb + 1 < NKB);
        if (pf) load_gmem(xv, wv, xg, W, kb + 1, tid);

        __syncthreads();   // stage (kb&1) fully written (stores from prev iter / prologue)

        const uint32_t sb   = sb0 + (uint32_t)(kb & 1) * STAGE_BYTES;
        const uint32_t aRow = sb + XHOFF + (uint32_t)tokrow * 128;

        #pragma unroll
        for (int s = 0; s < 4; ++s) {
            uint32_t oA = ((uint32_t)(s * 32) + half16) ^ swA;
            uint32_t aH[4], aL[4];
            ldsm4(aH, aRow + oA);
            ldsm4(aL, aRow + (XLOFF - XHOFF) + oA);

            const int krow = s * 16 + (lane & 15);
            const uint32_t swB  = ((uint32_t)krow & 7) << 4;
            const uint32_t bRow = sb + WHOFF + (uint32_t)krow * 128;

            #pragma unroll
            for (int b = 0; b < 2; ++b) {
                uint32_t oB = ((uint32_t)(wn * 64 + b * 32) + half16) ^ swB;
                uint32_t bH[4], bL[4];
                ldsm4t(bH, bRow + oB);
                ldsm4t(bL, bRow + (WLOFF - WHOFF) + oB);
                // 4 tiers: x0w0 + x0w1 + x1w0 + x1w1 (all into fp32 acc)
                mma16816(acc[b * 2],     aH, bH[0], bH[1]);
                mma16816(acc[b * 2],     aH, bL[0], bL[1]);
                mma16816(acc[b * 2],     aL, bH[0], bH[1]);
                mma16816(acc[b * 2],     aL, bL[0], bL[1]);
                mma16816(acc[b * 2 + 1], aH, bH[2], bH[3]);
                mma16816(acc[b * 2 + 1], aH, bL[2], bL[3]);
                mma16816(acc[b * 2 + 1], aL, bH[2], bH[3]);
                mma16816(acc[b * 2 + 1], aL, bL[2], bL[3]);
            }
        }

        if (pf)
            store_stage(dsm + ((kb + 1) & 1) * STAGE_BYTES, xv, wv, tid);
    }

    __syncthreads();   // all fragment reads done; reuse dsm as score matrix sc[tok*65+e]
    float* sc = (float*)dsm;

    // write sigmoid scores from C fragments
    // c0: (r, 2c) c1: (r, 2c+1) c2: (r+8, 2c) c3: (r+8, 2c+1), r = lane/4, c = lane%4
    #pragma unroll
    for (int nt = 0; nt < 4; ++nt) {
        #pragma unroll
        for (int i = 0; i < 4; ++i) {
            int row = wm * 16 + (lane >> 2) + ((i >> 1) ? 8 : 0);
            int col = wn * 32 + nt * 8 + (lane & 3) * 2 + (i & 1);
            sc[row * 65 + col] = 1.0f / (1.0f + expf(-acc[nt][i]));
        }
    }
    __syncthreads();

    // top-9 per token, flag near-ties, write top-8 outputs
    if (tid < TM) {
        const int tok = tid;
        const float* sr = sc + tok * 65;
        float bv[9];
        int   bi[9];
        #pragma unroll
        for (int k = 0; k < 9; ++k) { bv[k] = -INFINITY; bi[k] = 0; }
        for (int e = 0; e < NEXP; ++e) {
            float sv = sr[e] + bias_s[e];
            if (sv > bv[8]) {
                bv[8] = sv; bi[8] = e;
                #pragma unroll
                for (int j = 8; j > 0; --j) {
                    if (bv[j] > bv[j - 1]) {
                        float tv = bv[j]; bv[j] = bv[j - 1]; bv[j - 1] = tv;
                        int   ti = bi[j]; bi[j] = bi[j - 1]; bi[j - 1] = ti;
                    }
                }
            }
        }
        float mingap = INFINITY;
        #pragma unroll
        for (int j = 0; j < 8; ++j) {
            float gp = bv[j] - bv[j + 1];
            if (gp < mingap) mingap = gp;
        }
        const int gtok = t0 + tok;
        if (mingap < THETA) {
            int idx = atomicAdd(&g_refine_cnt, 1);
            g_refine_list[idx] = gtok;
        }
        float wsel[TOPK];
        float sum = 1e-20f;
        #pragma unroll
        for (int k = 0; k < TOPK; ++k) { wsel[k] = sr[bi[k]]; sum += wsel[k]; }
        float inv = RSCALE / sum;
        float* out_idx = out + (size_t)gtok * TOPK;
        float* out_w   = out + (size_t)T_TOKENS * TOPK + (size_t)gtok * TOPK;
        #pragma unroll
        for (int k = 0; k < TOPK; ++k) {
            out_idx[k] = (float)bi[k];
            out_w[k]   = wsel[k] * inv;
        }
    }
}

// ---------------- kernel 2: compensated-fp32 refinement ----------------
__global__ __launch_bounds__(256, 1)
void refine_kernel(const float* __restrict__ x,
                   const float* __restrict__ W,
                   const float* __restrict__ bias,
                   float* __restrict__ out)
{
    __shared__ double part[4][NEXP];
    __shared__ float  sc_s[NEXP];

    const int n = g_refine_cnt;
    const int e = threadIdx.x & 63;
    const int q = threadIdx.x >> 6;   // k-quarter 0..3

    for (int it = blockIdx.x; it < n; it += gridDim.x) {
        const int tok = g_refine_list[it];
        const float* xr = x + (size_t)tok * HID;

        // chunk-8 fma chains + scalar TwoSum compensation (intrinsics: fast-math-proof)
        float s = 0.0f, comp = 0.0f;
        const int kbeg = q * (HID / 4);
        for (int k = kbeg; k < kbeg + HID / 4; k += 8) {
            float ch = 0.0f;
            #pragma unroll
            for (int j = 0; j < 8; ++j)
                ch = __fmaf_rn(xr[k + j], W[(size_t)(k + j) * NEXP + e], ch);
            float sp = __fadd_rn(s, ch);
            float z  = __fsub_rn(sp, s);
            float e1 = __fsub_rn(ch, z);
            float t  = __fsub_rn(sp, z);
            float e2 = __fsub_rn(s, t);
            comp = __fadd_rn(comp, __fadd_rn(e1, e2));
            s = sp;
        }
        part[q][e] = (double)s + (double)comp;
        __syncthreads();

        if (q == 0) {
            double l = part[0][e] + part[1][e] + part[2][e] + part[3][e];
            float lf = (float)l;
            sc_s[e] = 1.0f / (1.0f + expf(-lf));
        }
        __syncthreads();

        if (threadIdx.x == 0) {
            float bv[TOPK];
            int   bi[TOPK];
            #pragma unroll
            for (int k = 0; k < TOPK; ++k) { bv[k] = -INFINITY; bi[k] = 0; }
            for (int ee = 0; ee < NEXP; ++ee) {
                float sv = sc_s[ee] + bias[ee];
                if (sv > bv[TOPK - 1]) {
                    bv[TOPK - 1] = sv; bi[TOPK - 1] = ee;
                    #pragma unroll
                    for (int j = TOPK - 1; j > 0; --j) {
                        if (bv[j] > bv[j - 1]) {
                            float tv = bv[j]; bv[j] = bv[j - 1]; bv[j - 1] = tv;
                            int   ti = bi[j]; bi[j] = bi[j - 1]; bi[j - 1] = ti;
                        }
                    }
                }
            }
            float wsel[TOPK];
            float sum = 1e-20f;
            #pragma unroll
            for (int k = 0; k < TOPK; ++k) { wsel[k] = sc_s[bi[k]]; sum += wsel[k]; }
            float inv = RSCALE / sum;
            float* out_idx = out + (size_t)tok * TOPK;
            float* out_w   = out + (size_t)T_TOKENS * TOPK + (size_t)tok * TOPK;
            #pragma unroll
            for (int k = 0; k < TOPK; ++k) {
                out_idx[k] = (float)bi[k];
                out_w[k]   = wsel[k] * inv;
            }
        }
        __syncthreads();
    }
}

extern "C" void kernel_launch(void* const* d_in, const int* in_sizes, int n_in,
                              void* d_out, int out_size)
{
    const float* x    = (const float*)d_in[0];
    const float* W    = (const float*)d_in[1];
    const float* bias = (const float*)d_in[2];
    float* out = (float*)d_out;

    cudaFuncSetAttribute(moe_gate_mma_kernel,
                         cudaFuncAttributeMaxDynamicSharedMemorySize, SMEM_TOTAL);

    reset_cnt_kernel<<<1, 1>>>();
    moe_gate_mma_kernel<<<T_TOKENS / TM, NTH, SMEM_TOTAL>>>(x, W, bias, out);
    refine_kernel<<<148, 256>>>(x, W, bias, out);
}